// round 11
// baseline (speedup 1.0000x reference)
#include <cuda_runtime.h>
#include <math.h>
#include <stdint.h>

#define BATCH  4
#define BC     32
#define C_     32
#define W_     14
#define HH     16
#define OUT_HW 29
#define NKL    288              // BC*3*3
#define CWW    6272             // C_*14*14
#define POS    196              // 14*14
#define G      8                // nkl group per block (two halves of 4)
#define NKLG   (NKL / G)        // 36

#define RING        5                              // ring slots
#define INFLIGHT    4                              // committed-ahead groups
#define NSTREAM     (G + 2)                        // mu, sv, 8x noise
#define SLOTS       196                            // 49 sites * 4 v
#define STREAM_BYTES (SLOTS * 16)                  // 3136
#define STAGE_BYTES  (NSTREAM * STREAM_BYTES)      // 31360
#define STAGE_F4     (NSTREAM * SLOTS)             // 1960 float4 per stage
#define NCHUNK      4
#define TOT_STAGES  (NCHUNK * C_)                  // 128
#define SW_BYTES    (G * C_ * 16 * 4)              // 16384
#define SMEM_BYTES  (RING * STAGE_BYTES + SW_BYTES)   // 173184

// sqrt(var) cache: 4 * 6272 * 16 floats = 1.6 MB
__device__ float g_sv[BATCH * CWW * HH];

__global__ void prep_kernel(const float* __restrict__ var,
                            float* __restrict__ out, int out_n4) {
    int idx = blockIdx.x * blockDim.x + threadIdx.x;
    const int sv_n4 = BATCH * CWW * HH / 4;
    if (idx < sv_n4) {
        float4 v = reinterpret_cast<const float4*>(var)[idx];
        float4 s;
        s.x = sqrtf(v.x); s.y = sqrtf(v.y);
        s.z = sqrtf(v.z); s.w = sqrtf(v.w);
        reinterpret_cast<float4*>(g_sv)[idx] = s;
    }
    if (idx < out_n4)
        reinterpret_cast<float4*>(out)[idx] = make_float4(0.f, 0.f, 0.f, 0.f);
}

__device__ __forceinline__ void cp_async16(uint32_t dst, const float4* src) {
    asm volatile("cp.async.cg.shared.global [%0], [%1], 16;\n"
                 :: "r"(dst), "l"(src) : "memory");
}
__device__ __forceinline__ void cp_commit() {
    asm volatile("cp.async.commit_group;\n" ::: "memory");
}
__device__ __forceinline__ void cp_wait3() {
    asm volatile("cp.async.wait_group 3;\n" ::: "memory");
}

__device__ __forceinline__ void fma4(float4& a, float s, const float4& b) {
    a.x = fmaf(s, b.x, a.x);
    a.y = fmaf(s, b.y, a.y);
    a.z = fmaf(s, b.z, a.z);
    a.w = fmaf(s, b.w, a.w);
}

// G=8 with smem-SHARED mu/sv: 512 threads. Stage = 10 streams x 196 float4.
// Copies are block-cooperative (each thread owns <=4 fixed (src,dst) pairs).
// Half A (tid<256, slots 0..195) computes g=0..3; half B (tid>=256) g=4..7;
// both read the SAME mu/sv smem bytes -> mu/sv hit L2 once per 8 nkl.
// One __syncthreads per stage publishes copies across threads (each thread's
// wait_group proves its own copies first). Ring has 5 slots with only 4
// groups in flight, so an in-flight write never targets the slot being read.
__global__ __launch_bounds__(512, 1) void conv_caps_kernel(
    const float* __restrict__ poses,   // mu: (b, CWW, 16)
    const float* __restrict__ Wt,      // (nkl, c, u, v)
    const float* __restrict__ noise,   // (b, nkl, CWW, 16)
    float* __restrict__ out)           // (b, BC, 29, 29, 16)
{
    extern __shared__ __align__(16) unsigned char smem_raw[];
    float* sW = reinterpret_cast<float*>(smem_raw + RING * STAGE_BYTES);

    const int nkl0 = blockIdx.x * G;
    const int b    = blockIdx.y;
    const int tid  = threadIdx.x;

    // W transposed to [g][c][v][u]: lane reads its 4 u-values as one LDS.128
    for (int t = tid; t < G * C_ * 16; t += 512) {
        int g  = t >> 9;
        int r  = t & 511;
        int c  = r >> 4;
        int u  = (r >> 2) & 3;
        int vv = r & 3;
        sW[((g * C_ + c) * 4 + vv) * 4 + u] = Wt[(nkl0 + g) * (C_ * 16) + r];
    }

    const size_t bq = (size_t)b * (CWW * HH / 4);
    const float4* mu4 = reinterpret_cast<const float4*>(poses) + bq;
    const float4* sv4 = reinterpret_cast<const float4*>(g_sv) + bq;
    const float4* nzb = reinterpret_cast<const float4*>(noise)
                      + (size_t)(b * NKL + nkl0) * (CWW * HH / 4);

    // Fixed copy descriptors: thread owns stage-float4 indices tid + q*512.
    const float4* qsrc[4];
    int  qsmem[4];
    bool qok[4];
#pragma unroll
    for (int q = 0; q < 4; q++) {
        const int u = tid + q * 512;
        qok[q] = (u < STAGE_F4);
        const int s  = qok[q] ? (u / SLOTS) : 0;
        const int sl = qok[q] ? (u % SLOTS) : 0;
        const float4* base = (s == 0) ? mu4
                           : (s == 1) ? sv4
                           : nzb + (size_t)(s - 2) * (CWW * HH / 4);
        qsrc[q]  = base + sl;
        qsmem[q] = s * STREAM_BYTES + sl * 16;
    }

    const uint32_t sb = (uint32_t)__cvta_generic_to_shared(smem_raw);

    auto issue = [&](int it) {
        const int chunk = it >> 5;
        const int c     = it & 31;
        const int off   = c * (POS * 4) + chunk * SLOTS;   // float4 units
        const uint32_t d = sb + (it % RING) * STAGE_BYTES;
#pragma unroll
        for (int q = 0; q < 4; q++)
            if (qok[q]) cp_async16(d + qsmem[q], qsrc[q] + off);
        cp_commit();
    };

    __syncthreads();   // sW ready before mainloop

#pragma unroll
    for (int p = 0; p < INFLIGHT; p++) issue(p);

    const int hb   = tid >> 8;          // 0 = half A (g 0-3), 1 = half B (g 4-7)
    const int lt   = tid & 255;
    const int slot = lt;                // compute slot
    const int v    = lt & 3;
    const bool cactive = (lt < SLOTS);
    // warps with all-32 compute lanes use full mask; the 196..223 boundary
    // warp has lanes 0-3 only (mask 0xF); lanes >=196 skip the reduce.
    const unsigned shfl_mask = (lt < 192) ? 0xffffffffu : 0x0000000Fu;

#pragma unroll 1
    for (int chunk = 0; chunk < NCHUNK; chunk++) {
        float4 acc[4][4];
#pragma unroll
        for (int g = 0; g < 4; g++)
#pragma unroll
            for (int u = 0; u < 4; u++)
                acc[g][u] = make_float4(0.f, 0.f, 0.f, 0.f);

#pragma unroll 1
        for (int c = 0; c < C_; c++) {
            const int it = chunk * C_ + c;
            cp_wait3();        // own copies of stage `it` complete
            __syncthreads();   // publish all threads' copies

            const float4* st = reinterpret_cast<const float4*>(
                smem_raw + (it % RING) * STAGE_BYTES);

            float4 mm = st[0 * SLOTS + slot];
            float4 ss = st[1 * SLOTS + slot];
            float4 n0 = st[(2 + hb * 4 + 0) * SLOTS + slot];
            float4 n1 = st[(2 + hb * 4 + 1) * SLOTS + slot];
            float4 n2 = st[(2 + hb * 4 + 2) * SLOTS + slot];
            float4 n3 = st[(2 + hb * 4 + 3) * SLOTS + slot];

            // Refill: targets ring slot (it+4)%5 != it%5 — never the slot any
            // thread is currently reading (all threads are past this stage's
            // barrier). Empty commit at the tail keeps counts uniform.
            if (it + INFLIGHT < TOT_STAGES) issue(it + INFLIGHT);
            else                            cp_commit();

            if (cactive) {
                const int gb = hb * 4;
                float4 vt;
                const float4* wv;

                vt.x = fmaf(ss.x, n0.x, mm.x);
                vt.y = fmaf(ss.y, n0.y, mm.y);
                vt.z = fmaf(ss.z, n0.z, mm.z);
                vt.w = fmaf(ss.w, n0.w, mm.w);
                wv = reinterpret_cast<const float4*>(&sW[(((gb + 0) * C_ + c) * 4 + v) * 4]);
                fma4(acc[0][0], wv->x, vt);
                fma4(acc[0][1], wv->y, vt);
                fma4(acc[0][2], wv->z, vt);
                fma4(acc[0][3], wv->w, vt);

                vt.x = fmaf(ss.x, n1.x, mm.x);
                vt.y = fmaf(ss.y, n1.y, mm.y);
                vt.z = fmaf(ss.z, n1.z, mm.z);
                vt.w = fmaf(ss.w, n1.w, mm.w);
                wv = reinterpret_cast<const float4*>(&sW[(((gb + 1) * C_ + c) * 4 + v) * 4]);
                fma4(acc[1][0], wv->x, vt);
                fma4(acc[1][1], wv->y, vt);
                fma4(acc[1][2], wv->z, vt);
                fma4(acc[1][3], wv->w, vt);

                vt.x = fmaf(ss.x, n2.x, mm.x);
                vt.y = fmaf(ss.y, n2.y, mm.y);
                vt.z = fmaf(ss.z, n2.z, mm.z);
                vt.w = fmaf(ss.w, n2.w, mm.w);
                wv = reinterpret_cast<const float4*>(&sW[(((gb + 2) * C_ + c) * 4 + v) * 4]);
                fma4(acc[2][0], wv->x, vt);
                fma4(acc[2][1], wv->y, vt);
                fma4(acc[2][2], wv->z, vt);
                fma4(acc[2][3], wv->w, vt);

                vt.x = fmaf(ss.x, n3.x, mm.x);
                vt.y = fmaf(ss.y, n3.y, mm.y);
                vt.z = fmaf(ss.z, n3.z, mm.z);
                vt.w = fmaf(ss.w, n3.w, mm.w);
                wv = reinterpret_cast<const float4*>(&sW[(((gb + 3) * C_ + c) * 4 + v) * 4]);
                fma4(acc[3][0], wv->x, vt);
                fma4(acc[3][1], wv->y, vt);
                fma4(acc[3][2], wv->z, vt);
                fma4(acc[3][3], wv->w, vt);
            }
        }

        // v-contraction: 2 butterfly rounds within each 4-lane site group.
        if (cactive) {
#pragma unroll
            for (int g = 0; g < 4; g++)
#pragma unroll
                for (int u = 0; u < 4; u++) {
                    float4 a = acc[g][u];
                    a.x += __shfl_xor_sync(shfl_mask, a.x, 1);
                    a.y += __shfl_xor_sync(shfl_mask, a.y, 1);
                    a.z += __shfl_xor_sync(shfl_mask, a.z, 1);
                    a.w += __shfl_xor_sync(shfl_mask, a.w, 1);
                    a.x += __shfl_xor_sync(shfl_mask, a.x, 2);
                    a.y += __shfl_xor_sync(shfl_mask, a.y, 2);
                    a.z += __shfl_xor_sync(shfl_mask, a.z, 2);
                    a.w += __shfl_xor_sync(shfl_mask, a.w, 2);
                    acc[g][u] = a;
                }

            const int site = chunk * 49 + (slot >> 2);
            const int j = site / W_;
            const int i = site % W_;
#pragma unroll
            for (int g = 0; g < 4; g++) {
                const int nkl = nkl0 + hb * 4 + g;
                const int n = nkl / 9;
                const int k = (nkl / 3) % 3;
                const int l = nkl % 3;
                const int r  = 2 * i + k;
                const int cc = 2 * j + l;
                float4 a = (v == 0) ? acc[g][0]
                         : (v == 1) ? acc[g][1]
                         : (v == 2) ? acc[g][2]
                                    : acc[g][3];
                float* o = out + ((((size_t)b * BC + n) * OUT_HW + r) * OUT_HW + cc) * HH
                               + v * 4;
                atomicAdd(o + 0, a.x);
                atomicAdd(o + 1, a.y);
                atomicAdd(o + 2, a.z);
                atomicAdd(o + 3, a.w);
            }
        }
    }
}

extern "C" void kernel_launch(void* const* d_in, const int* in_sizes, int n_in,
                              void* d_out, int out_size) {
    const float* poses = (const float*)d_in[0];
    const float* var   = (const float*)d_in[1];
    const float* Wt    = (const float*)d_in[2];
    const float* noise = (const float*)d_in[3];
    float* out = (float*)d_out;

    // Allow >48KB dynamic smem (idempotent attribute set; capture-safe).
    cudaFuncSetAttribute(conv_caps_kernel,
                         cudaFuncAttributeMaxDynamicSharedMemorySize, SMEM_BYTES);

    const int out_n4 = out_size / 4;
    const int pt = 256;
    const int pb = (out_n4 + pt - 1) / pt;
    prep_kernel<<<pb, pt>>>(var, out, out_n4);

    dim3 grid(NKLG, BATCH);   // 36 x 4 = 144 blocks, 1 CTA/SM, single wave
    conv_caps_kernel<<<grid, 512, SMEM_BYTES>>>(poses, Wt, noise, out);
}

// round 12
// speedup vs baseline: 1.1030x; 1.1030x over previous
#include <cuda_runtime.h>
#include <math.h>
#include <stdint.h>

#define BATCH  4
#define BC     32
#define C_     32
#define W_     14
#define HH     16
#define OUT_HW 29
#define NKL    288              // BC*3*3
#define CWW    6272             // C_*14*14
#define POS    196              // 14*14
#define G      4                // nkl group per block
#define NKLG   (NKL / G)        // 72
#define NBLOCKS 288

#define DSTAGE       4
#define NSTREAM      (G + 2)                      // mu, var, 4x noise
#define SLOTS        196                          // 49 sites * 4 v
#define STREAM_BYTES (SLOTS * 16)                 // 3136
#define STAGE_BYTES  (NSTREAM * STREAM_BYTES)     // 18816
#define NCHUNK       4
#define TOT_STAGES   (NCHUNK * C_)                // 128
#define SW_BYTES     (G * C_ * 16 * 4)            // 8192
#define SMEM_BYTES   (DSTAGE * STAGE_BYTES + SW_BYTES)  // 83456

#define OUTN4      430592                         // 4*32*29*29*16 / 4
#define ZSLICE     1496                           // ceil(OUTN4 / 288)
#define FIN_TARGET (SLOTS * NBLOCKS)              // 56448

// Launch-scoped handshake counters; every launch returns them to 0.
__device__ unsigned g_done = 0;
__device__ unsigned g_fin  = 0;

__device__ __forceinline__ void cp_async16(uint32_t dst, const float4* src) {
    asm volatile("cp.async.cg.shared.global [%0], [%1], 16;\n"
                 :: "r"(dst), "l"(src) : "memory");
}
__device__ __forceinline__ void cp_commit() {
    asm volatile("cp.async.commit_group;\n" ::: "memory");
}
__device__ __forceinline__ void cp_wait3() {
    asm volatile("cp.async.wait_group 3;\n" ::: "memory");
}
__device__ __forceinline__ float sqrt_ap(float x) {
    float r;
    asm("sqrt.approx.f32 %0, %1;" : "=f"(r) : "f"(x));
    return r;
}
__device__ __forceinline__ void fma4(float4& a, float s, const float4& b) {
    a.x = fmaf(s, b.x, a.x);
    a.y = fmaf(s, b.y, a.y);
    a.z = fmaf(s, b.z, a.z);
    a.w = fmaf(s, b.w, a.w);
}

// R7 per-thread cp.async pipeline, fully fused (no prep kernel):
//  - streams raw var; sqrt computed inline via MUFU sqrt.approx (~1e-7 rel)
//  - each block zeroes its exclusive 1/288 slice of out, signals g_done;
//    threads spin on g_done==288 just before their FIRST output atomic
//    (zeroing finishes ~20us before that point). All 288 blocks are
//    resident in one wave (2 CTAs/SM x 148 SMs >= 288), so no deadlock.
//  - warp-aggregated g_fin; last leader resets both counters (replay-safe).
__global__ __launch_bounds__(256, 2) void conv_caps_kernel(
    const float* __restrict__ poses,   // mu: (b, CWW, 16)
    const float* __restrict__ var,     // (b, CWW, 16)
    const float* __restrict__ Wt,      // (nkl, c, u, v)
    const float* __restrict__ noise,   // (b, nkl, CWW, 16)
    float* __restrict__ out)           // (b, BC, 29, 29, 16)
{
    extern __shared__ __align__(16) unsigned char smem_raw[];
    float* sW = reinterpret_cast<float*>(smem_raw + DSTAGE * STAGE_BYTES);

    const int nkl0 = blockIdx.x * G;
    const int b    = blockIdx.y;
    const int bid  = blockIdx.y * NKLG + blockIdx.x;
    const int tid  = threadIdx.x;

    const size_t bq = (size_t)b * (CWW * HH / 4);
    const float4* s0 = reinterpret_cast<const float4*>(poses) + bq;   // mu
    const float4* s1 = reinterpret_cast<const float4*>(var)   + bq;   // var
    const float4* s2 = reinterpret_cast<const float4*>(noise)
                     + (size_t)(b * NKL + nkl0) * (CWW * HH / 4);
    const float4* s3 = s2 + (CWW * HH / 4);
    const float4* s4 = s3 + (CWW * HH / 4);
    const float4* s5 = s4 + (CWW * HH / 4);

    const uint32_t sb = (uint32_t)__cvta_generic_to_shared(smem_raw) + tid * 16;

    auto issue = [&](int it) {
        const int chunk = it >> 5;
        const int c     = it & 31;
        const int fidx  = c * (POS * 4) + chunk * SLOTS + tid;
        const uint32_t d = sb + (it & (DSTAGE - 1)) * STAGE_BYTES;
        cp_async16(d + 0 * STREAM_BYTES, s0 + fidx);
        cp_async16(d + 1 * STREAM_BYTES, s1 + fidx);
        cp_async16(d + 2 * STREAM_BYTES, s2 + fidx);
        cp_async16(d + 3 * STREAM_BYTES, s3 + fidx);
        cp_async16(d + 4 * STREAM_BYTES, s4 + fidx);
        cp_async16(d + 5 * STREAM_BYTES, s5 + fidx);
        cp_commit();
    };

    // Prime the pipeline FIRST so the loads fly while we zero + stage W.
    if (tid < SLOTS) {
#pragma unroll
        for (int p = 0; p < DSTAGE; p++) issue(p);
    }

    // Zero this block's exclusive slice of out (all 256 threads).
    {
        float4* o4 = reinterpret_cast<float4*>(out);
        const float4 z = make_float4(0.f, 0.f, 0.f, 0.f);
        const int zb = bid * ZSLICE;
        const int ze = (zb + ZSLICE < OUTN4) ? zb + ZSLICE : OUTN4;
#pragma unroll 1
        for (int t = zb + tid; t < ze; t += 256) o4[t] = z;
    }

    // W transposed to [g][c][v][u] so a lane reads its 4 u-values as one LDS.128
    for (int t = tid; t < G * C_ * 16; t += 256) {
        int g  = t >> 9;
        int r  = t & 511;
        int c  = r >> 4;
        int u  = (r >> 2) & 3;
        int vv = r & 3;
        sW[((g * C_ + c) * 4 + vv) * 4 + u] = Wt[(nkl0 + g) * (C_ * 16) + r];
    }

    __threadfence();    // publish this thread's zero-stores device-wide
    __syncthreads();    // all threads' fenced stores done; sW ready
    if (tid == 0) atomicAdd(&g_done, 1u);

    if (tid >= SLOTS) return;   // no block-wide barriers below

    const int v = tid & 3;
    const unsigned shfl_mask = (tid < 192) ? 0xffffffffu : 0x0000000Fu;

#pragma unroll 1
    for (int chunk = 0; chunk < NCHUNK; chunk++) {
        float4 acc[G][4];
#pragma unroll
        for (int g = 0; g < G; g++)
#pragma unroll
            for (int u = 0; u < 4; u++)
                acc[g][u] = make_float4(0.f, 0.f, 0.f, 0.f);

#pragma unroll 1
        for (int c = 0; c < C_; c++) {
            const int it = chunk * C_ + c;
            cp_wait3();   // one group/iter => stage `it` is complete

            const float4* st = reinterpret_cast<const float4*>(
                smem_raw + (it & (DSTAGE - 1)) * STAGE_BYTES);
            float4 mm = st[0 * SLOTS + tid];
            float4 ss = st[1 * SLOTS + tid];   // raw var
            float4 n0 = st[2 * SLOTS + tid];
            float4 n1 = st[3 * SLOTS + tid];
            float4 n2 = st[4 * SLOTS + tid];
            float4 n3 = st[5 * SLOTS + tid];

            // Refill consumed slot; past the end, empty commit keeps the
            // group count advancing exactly once per iteration.
            if (it + DSTAGE < TOT_STAGES) issue(it + DSTAGE);
            else                          cp_commit();

            // sqrt(var) inline: 4 MUFU, reused across all 4 noise streams.
            ss.x = sqrt_ap(ss.x);
            ss.y = sqrt_ap(ss.y);
            ss.z = sqrt_ap(ss.z);
            ss.w = sqrt_ap(ss.w);

            float4 vt;
            const float4* wv;

            vt.x = fmaf(ss.x, n0.x, mm.x);
            vt.y = fmaf(ss.y, n0.y, mm.y);
            vt.z = fmaf(ss.z, n0.z, mm.z);
            vt.w = fmaf(ss.w, n0.w, mm.w);
            wv = reinterpret_cast<const float4*>(&sW[((0 * C_ + c) * 4 + v) * 4]);
            fma4(acc[0][0], wv->x, vt);
            fma4(acc[0][1], wv->y, vt);
            fma4(acc[0][2], wv->z, vt);
            fma4(acc[0][3], wv->w, vt);

            vt.x = fmaf(ss.x, n1.x, mm.x);
            vt.y = fmaf(ss.y, n1.y, mm.y);
            vt.z = fmaf(ss.z, n1.z, mm.z);
            vt.w = fmaf(ss.w, n1.w, mm.w);
            wv = reinterpret_cast<const float4*>(&sW[((1 * C_ + c) * 4 + v) * 4]);
            fma4(acc[1][0], wv->x, vt);
            fma4(acc[1][1], wv->y, vt);
            fma4(acc[1][2], wv->z, vt);
            fma4(acc[1][3], wv->w, vt);

            vt.x = fmaf(ss.x, n2.x, mm.x);
            vt.y = fmaf(ss.y, n2.y, mm.y);
            vt.z = fmaf(ss.z, n2.z, mm.z);
            vt.w = fmaf(ss.w, n2.w, mm.w);
            wv = reinterpret_cast<const float4*>(&sW[((2 * C_ + c) * 4 + v) * 4]);
            fma4(acc[2][0], wv->x, vt);
            fma4(acc[2][1], wv->y, vt);
            fma4(acc[2][2], wv->z, vt);
            fma4(acc[2][3], wv->w, vt);

            vt.x = fmaf(ss.x, n3.x, mm.x);
            vt.y = fmaf(ss.y, n3.y, mm.y);
            vt.z = fmaf(ss.z, n3.z, mm.z);
            vt.w = fmaf(ss.w, n3.w, mm.w);
            wv = reinterpret_cast<const float4*>(&sW[((3 * C_ + c) * 4 + v) * 4]);
            fma4(acc[3][0], wv->x, vt);
            fma4(acc[3][1], wv->y, vt);
            fma4(acc[3][2], wv->z, vt);
            fma4(acc[3][3], wv->w, vt);
        }

        // v-contraction across each 4-lane (site) group: 2 butterfly rounds.
#pragma unroll
        for (int g = 0; g < G; g++)
#pragma unroll
            for (int u = 0; u < 4; u++) {
                float4 a = acc[g][u];
                a.x += __shfl_xor_sync(shfl_mask, a.x, 1);
                a.y += __shfl_xor_sync(shfl_mask, a.y, 1);
                a.z += __shfl_xor_sync(shfl_mask, a.z, 1);
                a.w += __shfl_xor_sync(shfl_mask, a.w, 1);
                a.x += __shfl_xor_sync(shfl_mask, a.x, 2);
                a.y += __shfl_xor_sync(shfl_mask, a.y, 2);
                a.z += __shfl_xor_sync(shfl_mask, a.z, 2);
                a.w += __shfl_xor_sync(shfl_mask, a.w, 2);
                acc[g][u] = a;
            }

        // Before the very first output atomic, make sure every block has
        // finished zeroing. Zeroing completes within ~1us of launch; this
        // point is ~25% into the kernel, so the spin never iterates.
        if (chunk == 0) {
            while (*(volatile unsigned*)&g_done < NBLOCKS) { }
            __threadfence();
        }

        const int site = chunk * 49 + (tid >> 2);
        const int j = site / W_;
        const int i = site % W_;
#pragma unroll
        for (int g = 0; g < G; g++) {
            const int nkl = nkl0 + g;
            const int n = nkl / 9;
            const int k = (nkl / 3) % 3;
            const int l = nkl % 3;
            const int r  = 2 * i + k;
            const int cc = 2 * j + l;
            float4 a = (v == 0) ? acc[g][0]
                     : (v == 1) ? acc[g][1]
                     : (v == 2) ? acc[g][2]
                                : acc[g][3];
            float* o = out + ((((size_t)b * BC + n) * OUT_HW + r) * OUT_HW + cc) * HH
                           + v * 4;
            atomicAdd(o + 0, a.x);
            atomicAdd(o + 1, a.y);
            atomicAdd(o + 2, a.z);
            atomicAdd(o + 3, a.w);
        }
    }

    // Epilogue: warp-aggregated finish counter; the last leader resets both
    // counters so the next (graph-replayed) launch starts from zero state.
    {
        __threadfence();
        const unsigned mask   = __activemask();
        const unsigned leader = __ffs(mask) - 1u;
        const unsigned cnt    = __popc(mask);
        if ((threadIdx.x & 31u) == leader) {
            unsigned old = atomicAdd(&g_fin, cnt);
            if (old + cnt == FIN_TARGET) {
                g_fin  = 0;
                __threadfence();
                g_done = 0;
            }
        }
    }
}

extern "C" void kernel_launch(void* const* d_in, const int* in_sizes, int n_in,
                              void* d_out, int out_size) {
    const float* poses = (const float*)d_in[0];
    const float* var   = (const float*)d_in[1];
    const float* Wt    = (const float*)d_in[2];
    const float* noise = (const float*)d_in[3];
    float* out = (float*)d_out;

    // Allow >48KB dynamic smem (idempotent attribute set; capture-safe).
    cudaFuncSetAttribute(conv_caps_kernel,
                         cudaFuncAttributeMaxDynamicSharedMemorySize, SMEM_BYTES);

    dim3 grid(NKLG, BATCH);   // 288 blocks, one resident wave (2 CTAs/SM)
    conv_caps_kernel<<<grid, 256, SMEM_BYTES>>>(poses, var, Wt, noise, out);
}

// round 13
// speedup vs baseline: 1.1057x; 1.0024x over previous
#include <cuda_runtime.h>
#include <math.h>
#include <stdint.h>

#define BATCH  4
#define BC     32
#define C_     32
#define W_     14
#define HH     16
#define OUT_HW 29
#define NKL    288              // BC*3*3
#define CWW    6272             // C_*14*14
#define POS    196              // 14*14
#define G      4                // nkl group per block
#define NKLG   (NKL / G)        // 72
#define NBLOCKS 288

#define DSTAGE       4
#define NSTREAM      (G + 2)                      // mu, var, 4x noise
#define SLOTS        196                          // 49 sites * 4 v
#define STREAM_BYTES (SLOTS * 16)                 // 3136
#define STAGE_BYTES  (NSTREAM * STREAM_BYTES)     // 18816
#define NCHUNK       4
#define TOT_STAGES   (NCHUNK * C_)                // 128
#define SW_BYTES     (G * C_ * 16 * 4)            // 8192
#define SMEM_BYTES   (DSTAGE * STAGE_BYTES + SW_BYTES)  // 83456

#define OUTN4      430592                         // 4*32*29*29*16 / 4
#define ZSLICE     1496                           // ceil(OUTN4 / 288)
#define FIN_TARGET (SLOTS * NBLOCKS)              // 56448

typedef unsigned long long ull;

// Launch-scoped handshake counters; every launch returns them to 0.
__device__ unsigned g_done = 0;
__device__ unsigned g_fin  = 0;

__device__ __forceinline__ void cp_async16(uint32_t dst, const float4* src) {
    asm volatile("cp.async.cg.shared.global [%0], [%1], 16;\n"
                 :: "r"(dst), "l"(src) : "memory");
}
__device__ __forceinline__ void cp_commit() {
    asm volatile("cp.async.commit_group;\n" ::: "memory");
}
__device__ __forceinline__ void cp_wait3() {
    asm volatile("cp.async.wait_group 3;\n" ::: "memory");
}
__device__ __forceinline__ float sqrt_ap(float x) {
    float r;
    asm("sqrt.approx.f32 %0, %1;" : "=f"(r) : "f"(x));
    return r;
}

// Packed f32x2 helpers (FFMA2 is PTX-only; ptxas never auto-fuses).
#define LDS_V2U64(lo, hi, addr) \
    asm volatile("ld.shared.v2.u64 {%0, %1}, [%2];" \
                 : "=l"(lo), "=l"(hi) : "r"(addr))
#define FMA2(d, a, b, c) \
    asm("fma.rn.f32x2 %0, %1, %2, %3;" : "=l"(d) : "l"(a), "l"(b), "l"(c))
#define PACK2(d, x) \
    asm("mov.b64 %0, {%1, %1};" : "=l"(d) : "f"(x))
#define UNPACK2(x, y, d) \
    asm("mov.b64 {%0, %1}, %2;" : "=f"(x), "=f"(y) : "l"(d))

// Fused single kernel (R12 structure, slimmed):
//  - per-thread cp.async pipeline, no block barriers in mainloop
//  - inline sqrt.approx on streamed raw var
//  - fused zero of out: block zeroes its slice; publication via
//    __syncthreads + tid0 red.release.gpu; consumers ld.acquire.gpu spin
//    just before their first output atomic (never iterates in practice)
//  - inner loop fully in fma.rn.f32x2 (half the fma-pipe issue)
__global__ __launch_bounds__(256, 2) void conv_caps_kernel(
    const float* __restrict__ poses,   // mu: (b, CWW, 16)
    const float* __restrict__ var,     // (b, CWW, 16)
    const float* __restrict__ Wt,      // (nkl, c, u, v)
    const float* __restrict__ noise,   // (b, nkl, CWW, 16)
    float* __restrict__ out)           // (b, BC, 29, 29, 16)
{
    extern __shared__ __align__(16) unsigned char smem_raw[];
    float* sW = reinterpret_cast<float*>(smem_raw + DSTAGE * STAGE_BYTES);

    const int nkl0 = blockIdx.x * G;
    const int b    = blockIdx.y;
    const int bid  = blockIdx.y * NKLG + blockIdx.x;
    const int tid  = threadIdx.x;

    const size_t bq = (size_t)b * (CWW * HH / 4);
    const float4* s0 = reinterpret_cast<const float4*>(poses) + bq;   // mu
    const float4* s1 = reinterpret_cast<const float4*>(var)   + bq;   // var
    const float4* s2 = reinterpret_cast<const float4*>(noise)
                     + (size_t)(b * NKL + nkl0) * (CWW * HH / 4);
    const float4* s3 = s2 + (CWW * HH / 4);
    const float4* s4 = s3 + (CWW * HH / 4);
    const float4* s5 = s4 + (CWW * HH / 4);

    const uint32_t smem_b = (uint32_t)__cvta_generic_to_shared(smem_raw);
    const uint32_t sb     = smem_b + tid * 16;

    auto issue = [&](int it) {
        const int chunk = it >> 5;
        const int c     = it & 31;
        const int fidx  = c * (POS * 4) + chunk * SLOTS + tid;
        const uint32_t d = sb + (it & (DSTAGE - 1)) * STAGE_BYTES;
        cp_async16(d + 0 * STREAM_BYTES, s0 + fidx);
        cp_async16(d + 1 * STREAM_BYTES, s1 + fidx);
        cp_async16(d + 2 * STREAM_BYTES, s2 + fidx);
        cp_async16(d + 3 * STREAM_BYTES, s3 + fidx);
        cp_async16(d + 4 * STREAM_BYTES, s4 + fidx);
        cp_async16(d + 5 * STREAM_BYTES, s5 + fidx);
        cp_commit();
    };

    // Prime the pipeline FIRST so loads fly while we zero + stage W.
    if (tid < SLOTS) {
#pragma unroll
        for (int p = 0; p < DSTAGE; p++) issue(p);
    }

    // Zero this block's exclusive slice of out (all 256 threads).
    {
        float4* o4 = reinterpret_cast<float4*>(out);
        const float4 z = make_float4(0.f, 0.f, 0.f, 0.f);
        const int zb = bid * ZSLICE;
        const int ze = (zb + ZSLICE < OUTN4) ? zb + ZSLICE : OUTN4;
#pragma unroll 1
        for (int t = zb + tid; t < ze; t += 256) o4[t] = z;
    }

    // W transposed to [g][c][v][u] so a lane reads its 4 u-values as one LDS.128
    for (int t = tid; t < G * C_ * 16; t += 256) {
        int g  = t >> 9;
        int r  = t & 511;
        int c  = r >> 4;
        int u  = (r >> 2) & 3;
        int vv = r & 3;
        sW[((g * C_ + c) * 4 + vv) * 4 + u] = Wt[(nkl0 + g) * (C_ * 16) + r];
    }

    // Publish zero-stores: bar.sync gives intra-block happens-before into
    // tid0; tid0's release-RED makes all of them visible to acquirers.
    __syncthreads();
    if (tid == 0)
        asm volatile("red.release.gpu.global.add.u32 [%0], 1;"
                     :: "l"(&g_done) : "memory");

    if (tid >= SLOTS) return;   // no block-wide barriers below

    const int v = tid & 3;
    const unsigned shfl_mask = (tid < 192) ? 0xffffffffu : 0x0000000Fu;

#pragma unroll 1
    for (int chunk = 0; chunk < NCHUNK; chunk++) {
        ull accL[G][4], accH[G][4];
#pragma unroll
        for (int g = 0; g < G; g++)
#pragma unroll
            for (int u = 0; u < 4; u++) { accL[g][u] = 0ull; accH[g][u] = 0ull; }

#pragma unroll 1
        for (int c = 0; c < C_; c++) {
            const int it = chunk * C_ + c;
            cp_wait3();   // one group/iter => stage `it` is complete

            const uint32_t stb = smem_b + (it & (DSTAGE - 1)) * STAGE_BYTES
                               + tid * 16;
            ull mmL, mmH, ssL, ssH;
            ull nL0, nH0, nL1, nH1, nL2, nH2, nL3, nH3;
            LDS_V2U64(mmL, mmH, stb + 0 * STREAM_BYTES);
            LDS_V2U64(ssL, ssH, stb + 1 * STREAM_BYTES);
            LDS_V2U64(nL0, nH0, stb + 2 * STREAM_BYTES);
            LDS_V2U64(nL1, nH1, stb + 3 * STREAM_BYTES);
            LDS_V2U64(nL2, nH2, stb + 4 * STREAM_BYTES);
            LDS_V2U64(nL3, nH3, stb + 5 * STREAM_BYTES);

            // Refill consumed slot; past the end, empty commit keeps the
            // group count advancing exactly once per iteration.
            if (it + DSTAGE < TOT_STAGES) issue(it + DSTAGE);
            else                          cp_commit();

            // sqrt(var): unpack -> 4x MUFU -> repack
            {
                float a0, a1, a2, a3;
                UNPACK2(a0, a1, ssL);
                UNPACK2(a2, a3, ssH);
                a0 = sqrt_ap(a0); a1 = sqrt_ap(a1);
                a2 = sqrt_ap(a2); a3 = sqrt_ap(a3);
                asm("mov.b64 %0, {%1, %2};" : "=l"(ssL) : "f"(a0), "f"(a1));
                asm("mov.b64 %0, {%1, %2};" : "=l"(ssH) : "f"(a2), "f"(a3));
            }

#pragma unroll
            for (int g = 0; g < G; g++) {
                ull nLg = (g == 0) ? nL0 : (g == 1) ? nL1 : (g == 2) ? nL2 : nL3;
                ull nHg = (g == 0) ? nH0 : (g == 1) ? nH1 : (g == 2) ? nH2 : nH3;
                ull vtL, vtH;
                FMA2(vtL, ssL, nLg, mmL);   // vote = mu + sqrt(var)*noise
                FMA2(vtH, ssH, nHg, mmH);

                const float4 w4 = *reinterpret_cast<const float4*>(
                    &sW[((g * C_ + c) * 4 + v) * 4]);
                ull w0, w1, w2, w3;
                PACK2(w0, w4.x); PACK2(w1, w4.y);
                PACK2(w2, w4.z); PACK2(w3, w4.w);
                FMA2(accL[g][0], w0, vtL, accL[g][0]);
                FMA2(accH[g][0], w0, vtH, accH[g][0]);
                FMA2(accL[g][1], w1, vtL, accL[g][1]);
                FMA2(accH[g][1], w1, vtH, accH[g][1]);
                FMA2(accL[g][2], w2, vtL, accL[g][2]);
                FMA2(accH[g][2], w2, vtH, accH[g][2]);
                FMA2(accL[g][3], w3, vtL, accL[g][3]);
                FMA2(accH[g][3], w3, vtH, accH[g][3]);
            }
        }

        // Unpack, then v-contraction: 2 butterfly rounds per 4-lane group.
        float4 acc[G][4];
#pragma unroll
        for (int g = 0; g < G; g++)
#pragma unroll
            for (int u = 0; u < 4; u++) {
                float4 a;
                UNPACK2(a.x, a.y, accL[g][u]);
                UNPACK2(a.z, a.w, accH[g][u]);
                a.x += __shfl_xor_sync(shfl_mask, a.x, 1);
                a.y += __shfl_xor_sync(shfl_mask, a.y, 1);
                a.z += __shfl_xor_sync(shfl_mask, a.z, 1);
                a.w += __shfl_xor_sync(shfl_mask, a.w, 1);
                a.x += __shfl_xor_sync(shfl_mask, a.x, 2);
                a.y += __shfl_xor_sync(shfl_mask, a.y, 2);
                a.z += __shfl_xor_sync(shfl_mask, a.z, 2);
                a.w += __shfl_xor_sync(shfl_mask, a.w, 2);
                acc[g][u] = a;
            }

        // Before the first output atomic, ensure every block finished its
        // zero slice. Acquire-load pairs with the release-RED above.
        if (chunk == 0) {
            unsigned d;
            do {
                asm volatile("ld.acquire.gpu.global.u32 %0, [%1];"
                             : "=r"(d) : "l"(&g_done) : "memory");
            } while (d < NBLOCKS);
        }

        const int site = chunk * 49 + (tid >> 2);
        const int j = site / W_;
        const int i = site % W_;
#pragma unroll
        for (int g = 0; g < G; g++) {
            const int nkl = nkl0 + g;
            const int n = nkl / 9;
            const int k = (nkl / 3) % 3;
            const int l = nkl % 3;
            const int r  = 2 * i + k;
            const int cc = 2 * j + l;
            float4 a = (v == 0) ? acc[g][0]
                     : (v == 1) ? acc[g][1]
                     : (v == 2) ? acc[g][2]
                                : acc[g][3];
            float* o = out + ((((size_t)b * BC + n) * OUT_HW + r) * OUT_HW + cc) * HH
                           + v * 4;
            atomicAdd(o + 0, a.x);
            atomicAdd(o + 1, a.y);
            atomicAdd(o + 2, a.z);
            atomicAdd(o + 3, a.w);
        }
    }

    // Epilogue: warp-aggregated finish counter; the last leader resets both
    // counters so the next (graph-replayed) launch starts from zero state.
    {
        __threadfence();
        const unsigned mask   = __activemask();
        const unsigned leader = __ffs(mask) - 1u;
        const unsigned cnt    = __popc(mask);
        if ((threadIdx.x & 31u) == leader) {
            unsigned old = atomicAdd(&g_fin, cnt);
            if (old + cnt == FIN_TARGET) {
                g_fin  = 0;
                __threadfence();
                g_done = 0;
            }
        }
    }
}

extern "C" void kernel_launch(void* const* d_in, const int* in_sizes, int n_in,
                              void* d_out, int out_size) {
    const float* poses = (const float*)d_in[0];
    const float* var   = (const float*)d_in[1];
    const float* Wt    = (const float*)d_in[2];
    const float* noise = (const float*)d_in[3];
    float* out = (float*)d_out;

    // Allow >48KB dynamic smem (idempotent attribute set; capture-safe).
    cudaFuncSetAttribute(conv_caps_kernel,
                         cudaFuncAttributeMaxDynamicSharedMemorySize, SMEM_BYTES);

    dim3 grid(NKLG, BATCH);   // 288 blocks, one resident wave (2 CTAs/SM)
    conv_caps_kernel<<<grid, 256, SMEM_BYTES>>>(poses, var, Wt, noise, out);
}

// round 16
// speedup vs baseline: 1.1811x; 1.0682x over previous
#include <cuda_runtime.h>
#include <math.h>
#include <stdint.h>

#define BATCH  4
#define BC     32
#define C_     32
#define W_     14
#define HH     16
#define OUT_HW 29
#define NKL    288              // BC*3*3
#define CWW    6272             // C_*14*14
#define POS    196              // 14*14
#define G      4                // nkl group per block
#define NKLG   (NKL / G)        // 72

#define RING         5
#define NSTREAM      (G + 2)                      // mu, sv, 4x noise
#define SLOTS        196                          // 49 sites * 4 v
#define STREAM_BYTES (SLOTS * 16)                 // 3136
#define STAGE_BYTES  (NSTREAM * STREAM_BYTES)     // 18816
#define NCHUNK       4
#define TOT_STAGES   (NCHUNK * C_)                // 128
#define SW_BYTES     (G * C_ * 16 * 4)            // 8192
#define SMEM_BAR     (RING * STAGE_BYTES + SW_BYTES)    // 102272 (16-aligned)
#define SMEM_BYTES   (SMEM_BAR + RING * 16)             // 102352

// sqrt(var) cache: 4 * 6272 * 16 floats = 1.6 MB
__device__ float g_sv[BATCH * CWW * HH];

__global__ void prep_kernel(const float* __restrict__ var,
                            float* __restrict__ out, int out_n4) {
    int idx = blockIdx.x * blockDim.x + threadIdx.x;
    const int sv_n4 = BATCH * CWW * HH / 4;
    if (idx < sv_n4) {
        float4 v = reinterpret_cast<const float4*>(var)[idx];
        float4 s;
        s.x = sqrtf(v.x); s.y = sqrtf(v.y);
        s.z = sqrtf(v.z); s.w = sqrtf(v.w);
        reinterpret_cast<float4*>(g_sv)[idx] = s;
    }
    if (idx < out_n4)
        reinterpret_cast<float4*>(out)[idx] = make_float4(0.f, 0.f, 0.f, 0.f);
}

// ---- mbarrier / bulk-copy primitives ----
#define MBAR_INIT(addr, cnt) \
    asm volatile("mbarrier.init.shared.b64 [%0], %1;" \
                 :: "r"(addr), "r"(cnt) : "memory")
#define MBAR_EXPECT_TX(addr, tx) \
    asm volatile("mbarrier.arrive.expect_tx.shared.b64 _, [%0], %1;" \
                 :: "r"(addr), "r"(tx) : "memory")
#define MBAR_ARRIVE(addr) \
    asm volatile("mbarrier.arrive.shared.b64 _, [%0];" \
                 :: "r"(addr) : "memory")
#define CP_BULK(dst, src, bytes, mbar) \
    asm volatile("cp.async.bulk.shared::cta.global.mbarrier::complete_tx::bytes " \
                 "[%0], [%1], %2, [%3];" \
                 :: "r"(dst), "l"(src), "r"(bytes), "r"(mbar) : "memory")

// RACE-FREE waits: per-lane C++ loop around try_wait -> selp. The compiler
// emits proper DIVERGENT branches, so a lane that sampled "not ready" can
// never be dragged past the wait by other lanes (the R15 bra.uni bug).
__device__ __forceinline__ void mbar_wait_acq(uint32_t addr, int parity) {
    unsigned done;
    do {
        asm volatile(
            "{\n\t.reg .pred p;\n\t"
            "mbarrier.try_wait.parity.acquire.cta.shared::cta.b64 p, [%1], %2, 0x989680;\n\t"
            "selp.b32 %0, 1, 0, p;\n\t}"
            : "=r"(done) : "r"(addr), "r"((unsigned)parity) : "memory");
    } while (!done);
}
// relaxed: producer-only; post-wait accesses are async-proxy bulk copies.
__device__ __forceinline__ void mbar_wait_rlx(uint32_t addr, int parity) {
    unsigned done;
    do {
        asm volatile(
            "{\n\t.reg .pred p;\n\t"
            "mbarrier.try_wait.parity.relaxed.cta.shared::cta.b64 p, [%1], %2, 0x989680;\n\t"
            "selp.b32 %0, 1, 0, p;\n\t}"
            : "=r"(done) : "r"(addr), "r"((unsigned)parity) : "memory");
    } while (!done);
}

__device__ __forceinline__ void fma4(float4& a, float s, const float4& b) {
    a.x = fmaf(s, b.x, a.x);
    a.y = fmaf(s, b.y, a.y);
    a.z = fmaf(s, b.z, a.z);
    a.w = fmaf(s, b.w, a.w);
}

// Producer/consumer bulk pipeline:
//  - producer = tid 224 (lane 0 of otherwise-dead warp 7): per stage waits
//    empty[s] (relaxed), arms full[s] with expect_tx(18816B), issues 6x
//    cp.async.bulk of 3136 CONTIGUOUS bytes (one per stream). 5-deep ring.
//  - consumers = tids 0..195: acquire-wait full[s] parity, LDS their own
//    6x16B, arrive on empty[s] (196 arrivals re-open the slot), compute.
//  - no __syncthreads in the mainloop; 2 CTAs/SM cover each other's waits.
__global__ __launch_bounds__(256, 2) void conv_caps_kernel(
    const float* __restrict__ poses,   // mu: (b, CWW, 16)
    const float* __restrict__ Wt,      // (nkl, c, u, v)
    const float* __restrict__ noise,   // (b, nkl, CWW, 16)
    float* __restrict__ out)           // (b, BC, 29, 29, 16)
{
    extern __shared__ __align__(16) unsigned char smem_raw[];
    float* sW = reinterpret_cast<float*>(smem_raw + RING * STAGE_BYTES);

    const int nkl0 = blockIdx.x * G;
    const int b    = blockIdx.y;
    const int tid  = threadIdx.x;

    const uint32_t smem_b = (uint32_t)__cvta_generic_to_shared(smem_raw);
    const uint32_t barb   = smem_b + SMEM_BAR;
    auto fullb  = [&](int s) { return barb + s * 16; };
    auto emptyb = [&](int s) { return barb + s * 16 + 8; };

    // W transposed to [g][c][v][u] so a lane reads its 4 u-values as one LDS.128
    for (int t = tid; t < G * C_ * 16; t += 256) {
        int g  = t >> 9;
        int r  = t & 511;
        int c  = r >> 4;
        int u  = (r >> 2) & 3;
        int vv = r & 3;
        sW[((g * C_ + c) * 4 + vv) * 4 + u] = Wt[(nkl0 + g) * (C_ * 16) + r];
    }
    if (tid == 0) {
#pragma unroll
        for (int s = 0; s < RING; s++) {
            MBAR_INIT(fullb(s), 1);        // producer's expect_tx arrive
            MBAR_INIT(emptyb(s), SLOTS);   // 196 consumer arrivals
        }
    }
    __syncthreads();   // barriers + sW visible; last block-wide sync

    if (tid == 224) {
        // ---- producer ----
        const size_t bq = (size_t)b * (CWW * HH / 4);
        const float4* s0 = reinterpret_cast<const float4*>(poses) + bq;
        const float4* s1 = reinterpret_cast<const float4*>(g_sv) + bq;
        const float4* s2 = reinterpret_cast<const float4*>(noise)
                         + (size_t)(b * NKL + nkl0) * (CWW * HH / 4);
        const float4* s3 = s2 + (CWW * HH / 4);
        const float4* s4 = s3 + (CWW * HH / 4);
        const float4* s5 = s4 + (CWW * HH / 4);

        int eslot = 0, ephase = 0;
#pragma unroll 1
        for (int it = 0; it < TOT_STAGES; it++) {
            const int s = it % RING;
            if (it >= RING) {
                mbar_wait_rlx(emptyb(eslot), ephase);
                if (++eslot == RING) { eslot = 0; ephase ^= 1; }
            }
            const int chunk = it >> 5;
            const int c     = it & 31;
            const int off   = c * (POS * 4) + chunk * SLOTS;   // float4 units
            const uint32_t d = smem_b + s * STAGE_BYTES;
            MBAR_EXPECT_TX(fullb(s), (uint32_t)STAGE_BYTES);
            CP_BULK(d + 0 * STREAM_BYTES, s0 + off, STREAM_BYTES, fullb(s));
            CP_BULK(d + 1 * STREAM_BYTES, s1 + off, STREAM_BYTES, fullb(s));
            CP_BULK(d + 2 * STREAM_BYTES, s2 + off, STREAM_BYTES, fullb(s));
            CP_BULK(d + 3 * STREAM_BYTES, s3 + off, STREAM_BYTES, fullb(s));
            CP_BULK(d + 4 * STREAM_BYTES, s4 + off, STREAM_BYTES, fullb(s));
            CP_BULK(d + 5 * STREAM_BYTES, s5 + off, STREAM_BYTES, fullb(s));
        }
        return;
    }
    if (tid >= SLOTS) return;   // dead lanes (196-223, 225-255)

    // ---- consumers ----
    const int v = tid & 3;
    const unsigned shfl_mask = (tid < 192) ? 0xffffffffu : 0x0000000Fu;

    int fslot = 0, fphase = 0;

#pragma unroll 1
    for (int chunk = 0; chunk < NCHUNK; chunk++) {
        float4 acc[G][4];
#pragma unroll
        for (int g = 0; g < G; g++)
#pragma unroll
            for (int u = 0; u < 4; u++)
                acc[g][u] = make_float4(0.f, 0.f, 0.f, 0.f);

#pragma unroll 1
        for (int c = 0; c < C_; c++) {
            mbar_wait_acq(fullb(fslot), fphase);

            const float4* st = reinterpret_cast<const float4*>(
                smem_raw + fslot * STAGE_BYTES);
            float4 mm = st[0 * SLOTS + tid];
            float4 ss = st[1 * SLOTS + tid];
            float4 n0 = st[2 * SLOTS + tid];
            float4 n1 = st[3 * SLOTS + tid];
            float4 n2 = st[4 * SLOTS + tid];
            float4 n3 = st[5 * SLOTS + tid];

            // Reads done -> release the slot for the producer (arrive has
            // release semantics; smem ops retire in order per thread).
            MBAR_ARRIVE(emptyb(fslot));
            if (++fslot == RING) { fslot = 0; fphase ^= 1; }

            float4 vt;
            const float4* wv;

            vt.x = fmaf(ss.x, n0.x, mm.x);
            vt.y = fmaf(ss.y, n0.y, mm.y);
            vt.z = fmaf(ss.z, n0.z, mm.z);
            vt.w = fmaf(ss.w, n0.w, mm.w);
            wv = reinterpret_cast<const float4*>(&sW[((0 * C_ + c) * 4 + v) * 4]);
            fma4(acc[0][0], wv->x, vt);
            fma4(acc[0][1], wv->y, vt);
            fma4(acc[0][2], wv->z, vt);
            fma4(acc[0][3], wv->w, vt);

            vt.x = fmaf(ss.x, n1.x, mm.x);
            vt.y = fmaf(ss.y, n1.y, mm.y);
            vt.z = fmaf(ss.z, n1.z, mm.z);
            vt.w = fmaf(ss.w, n1.w, mm.w);
            wv = reinterpret_cast<const float4*>(&sW[((1 * C_ + c) * 4 + v) * 4]);
            fma4(acc[1][0], wv->x, vt);
            fma4(acc[1][1], wv->y, vt);
            fma4(acc[1][2], wv->z, vt);
            fma4(acc[1][3], wv->w, vt);

            vt.x = fmaf(ss.x, n2.x, mm.x);
            vt.y = fmaf(ss.y, n2.y, mm.y);
            vt.z = fmaf(ss.z, n2.z, mm.z);
            vt.w = fmaf(ss.w, n2.w, mm.w);
            wv = reinterpret_cast<const float4*>(&sW[((2 * C_ + c) * 4 + v) * 4]);
            fma4(acc[2][0], wv->x, vt);
            fma4(acc[2][1], wv->y, vt);
            fma4(acc[2][2], wv->z, vt);
            fma4(acc[2][3], wv->w, vt);

            vt.x = fmaf(ss.x, n3.x, mm.x);
            vt.y = fmaf(ss.y, n3.y, mm.y);
            vt.z = fmaf(ss.z, n3.z, mm.z);
            vt.w = fmaf(ss.w, n3.w, mm.w);
            wv = reinterpret_cast<const float4*>(&sW[((3 * C_ + c) * 4 + v) * 4]);
            fma4(acc[3][0], wv->x, vt);
            fma4(acc[3][1], wv->y, vt);
            fma4(acc[3][2], wv->z, vt);
            fma4(acc[3][3], wv->w, vt);
        }

        // v-contraction across each 4-lane (site) group: 2 butterfly rounds.
#pragma unroll
        for (int g = 0; g < G; g++)
#pragma unroll
            for (int u = 0; u < 4; u++) {
                float4 a = acc[g][u];
                a.x += __shfl_xor_sync(shfl_mask, a.x, 1);
                a.y += __shfl_xor_sync(shfl_mask, a.y, 1);
                a.z += __shfl_xor_sync(shfl_mask, a.z, 1);
                a.w += __shfl_xor_sync(shfl_mask, a.w, 1);
                a.x += __shfl_xor_sync(shfl_mask, a.x, 2);
                a.y += __shfl_xor_sync(shfl_mask, a.y, 2);
                a.z += __shfl_xor_sync(shfl_mask, a.z, 2);
                a.w += __shfl_xor_sync(shfl_mask, a.w, 2);
                acc[g][u] = a;
            }

        const int site = chunk * 49 + (tid >> 2);
        const int j = site / W_;
        const int i = site % W_;
#pragma unroll
        for (int g = 0; g < G; g++) {
            const int nkl = nkl0 + g;
            const int n = nkl / 9;
            const int k = (nkl / 3) % 3;
            const int l = nkl % 3;
            const int r  = 2 * i + k;
            const int cc = 2 * j + l;
            // lane v scatters the u==v float4 (group covers all 16 values)
            float4 a = (v == 0) ? acc[g][0]
                     : (v == 1) ? acc[g][1]
                     : (v == 2) ? acc[g][2]
                                : acc[g][3];
            float* o = out + ((((size_t)b * BC + n) * OUT_HW + r) * OUT_HW + cc) * HH
                           + v * 4;
            atomicAdd(o + 0, a.x);
            atomicAdd(o + 1, a.y);
            atomicAdd(o + 2, a.z);
            atomicAdd(o + 3, a.w);
        }
    }
}

extern "C" void kernel_launch(void* const* d_in, const int* in_sizes, int n_in,
                              void* d_out, int out_size) {
    const float* poses = (const float*)d_in[0];
    const float* var   = (const float*)d_in[1];
    const float* Wt    = (const float*)d_in[2];
    const float* noise = (const float*)d_in[3];
    float* out = (float*)d_out;

    // Allow >48KB dynamic smem (idempotent attribute set; capture-safe).
    cudaFuncSetAttribute(conv_caps_kernel,
                         cudaFuncAttributeMaxDynamicSharedMemorySize, SMEM_BYTES);

    const int out_n4 = out_size / 4;
    const int pt = 256;
    const int pb = (out_n4 + pt - 1) / pt;
    prep_kernel<<<pb, pt>>>(var, out, out_n4);

    dim3 grid(NKLG, BATCH);   // 288 blocks, one resident wave (2 CTAs/SM)
    conv_caps_kernel<<<grid, 256, SMEM_BYTES>>>(poses, Wt, noise, out);
}

// round 17
// speedup vs baseline: 1.1886x; 1.0063x over previous
#include <cuda_runtime.h>
#include <math.h>
#include <stdint.h>

#define BATCH  4
#define BC     32
#define C_     32
#define W_     14
#define HH     16
#define OUT_HW 29
#define NKL    288              // BC*3*3
#define CWW    6272             // C_*14*14
#define POS    196              // 14*14
#define G      4                // nkl group per block
#define NKLG   (NKL / G)        // 72

#define RING         5
#define NSTREAM      (G + 2)                      // mu, sv, 4x noise
#define SLOTS        196                          // 49 sites * 4 v
#define STREAM_BYTES (SLOTS * 16)                 // 3136
#define STAGE_BYTES  (NSTREAM * STREAM_BYTES)     // 18816
#define NCHUNK       4
#define TOT_STAGES   (NCHUNK * C_)                // 128
#define SW_BYTES     (G * C_ * 16 * 4)            // 8192
#define SMEM_BAR     (RING * STAGE_BYTES + SW_BYTES)    // 102272 (16-aligned)
#define SMEM_BYTES   (SMEM_BAR + RING * 16)             // 102352

// sqrt(var) cache: 4 * 6272 * 16 floats = 1.6 MB
__device__ float g_sv[BATCH * CWW * HH];

__global__ void prep_kernel(const float* __restrict__ var,
                            float* __restrict__ out, int out_n4) {
    int idx = blockIdx.x * blockDim.x + threadIdx.x;
    const int sv_n4 = BATCH * CWW * HH / 4;
    if (idx < sv_n4) {
        float4 v = reinterpret_cast<const float4*>(var)[idx];
        float4 s;
        s.x = sqrtf(v.x); s.y = sqrtf(v.y);
        s.z = sqrtf(v.z); s.w = sqrtf(v.w);
        reinterpret_cast<float4*>(g_sv)[idx] = s;
    }
    if (idx < out_n4)
        reinterpret_cast<float4*>(out)[idx] = make_float4(0.f, 0.f, 0.f, 0.f);
}

// ---- mbarrier / bulk-copy primitives ----
#define MBAR_INIT(addr, cnt) \
    asm volatile("mbarrier.init.shared.b64 [%0], %1;" \
                 :: "r"(addr), "r"(cnt) : "memory")
#define MBAR_EXPECT_TX(addr, tx) \
    asm volatile("mbarrier.arrive.expect_tx.shared.b64 _, [%0], %1;" \
                 :: "r"(addr), "r"(tx) : "memory")
#define MBAR_ARRIVE(addr) \
    asm volatile("mbarrier.arrive.shared.b64 _, [%0];" \
                 :: "r"(addr) : "memory")
#define CP_BULK(dst, src, bytes, mbar) \
    asm volatile("cp.async.bulk.shared::cta.global.mbarrier::complete_tx::bytes " \
                 "[%0], [%1], %2, [%3];" \
                 :: "r"(dst), "l"(src), "r"(bytes), "r"(mbar) : "memory")

// Vectorized global reduction (sm_90+): one 16B atomic add per float4.
#define REDV4(ptr, a) \
    asm volatile("red.global.add.v4.f32 [%0], {%1, %2, %3, %4};" \
                 :: "l"(ptr), "f"((a).x), "f"((a).y), "f"((a).z), "f"((a).w) \
                 : "memory")

// RACE-FREE waits: per-lane C++ loop around try_wait -> selp (divergent
// branches; a "not ready" lane can never be dragged past the wait).
__device__ __forceinline__ void mbar_wait_acq(uint32_t addr, int parity) {
    unsigned done;
    do {
        asm volatile(
            "{\n\t.reg .pred p;\n\t"
            "mbarrier.try_wait.parity.acquire.cta.shared::cta.b64 p, [%1], %2, 0x989680;\n\t"
            "selp.b32 %0, 1, 0, p;\n\t}"
            : "=r"(done) : "r"(addr), "r"((unsigned)parity) : "memory");
    } while (!done);
}
__device__ __forceinline__ void mbar_wait_rlx(uint32_t addr, int parity) {
    unsigned done;
    do {
        asm volatile(
            "{\n\t.reg .pred p;\n\t"
            "mbarrier.try_wait.parity.relaxed.cta.shared::cta.b64 p, [%1], %2, 0x989680;\n\t"
            "selp.b32 %0, 1, 0, p;\n\t}"
            : "=r"(done) : "r"(addr), "r"((unsigned)parity) : "memory");
    } while (!done);
}

__device__ __forceinline__ void fma4(float4& a, float s, const float4& b) {
    a.x = fmaf(s, b.x, a.x);
    a.y = fmaf(s, b.y, a.y);
    a.z = fmaf(s, b.z, a.z);
    a.w = fmaf(s, b.w, a.w);
}

// Producer/consumer bulk pipeline (R16 WIN structure):
//  - producer = tid 224: per stage waits empty[s] (relaxed), arms full[s]
//    expect_tx(18816B), issues 6x cp.async.bulk of 3136 contiguous bytes.
//  - consumers = tids 0..195: acquire-wait full[s], LDS 6x16B, arrive
//    empty[s], compute. No __syncthreads in the mainloop.
//  - output scatter via red.global.add.v4.f32 (1 op per 16B, 4x fewer
//    atomic ops than scalar atomicAdd).
__global__ __launch_bounds__(256, 2) void conv_caps_kernel(
    const float* __restrict__ poses,   // mu: (b, CWW, 16)
    const float* __restrict__ Wt,      // (nkl, c, u, v)
    const float* __restrict__ noise,   // (b, nkl, CWW, 16)
    float* __restrict__ out)           // (b, BC, 29, 29, 16)
{
    extern __shared__ __align__(16) unsigned char smem_raw[];
    float* sW = reinterpret_cast<float*>(smem_raw + RING * STAGE_BYTES);

    const int nkl0 = blockIdx.x * G;
    const int b    = blockIdx.y;
    const int tid  = threadIdx.x;

    const uint32_t smem_b = (uint32_t)__cvta_generic_to_shared(smem_raw);
    const uint32_t barb   = smem_b + SMEM_BAR;
    auto fullb  = [&](int s) { return barb + s * 16; };
    auto emptyb = [&](int s) { return barb + s * 16 + 8; };

    // W transposed to [g][c][v][u] so a lane reads its 4 u-values as one LDS.128
    for (int t = tid; t < G * C_ * 16; t += 256) {
        int g  = t >> 9;
        int r  = t & 511;
        int c  = r >> 4;
        int u  = (r >> 2) & 3;
        int vv = r & 3;
        sW[((g * C_ + c) * 4 + vv) * 4 + u] = Wt[(nkl0 + g) * (C_ * 16) + r];
    }
    if (tid == 0) {
#pragma unroll
        for (int s = 0; s < RING; s++) {
            MBAR_INIT(fullb(s), 1);        // producer's expect_tx arrive
            MBAR_INIT(emptyb(s), SLOTS);   // 196 consumer arrivals
        }
    }
    __syncthreads();   // barriers + sW visible; last block-wide sync

    if (tid == 224) {
        // ---- producer ----
        const size_t bq = (size_t)b * (CWW * HH / 4);
        const float4* s0 = reinterpret_cast<const float4*>(poses) + bq;
        const float4* s1 = reinterpret_cast<const float4*>(g_sv) + bq;
        const float4* s2 = reinterpret_cast<const float4*>(noise)
                         + (size_t)(b * NKL + nkl0) * (CWW * HH / 4);
        const float4* s3 = s2 + (CWW * HH / 4);
        const float4* s4 = s3 + (CWW * HH / 4);
        const float4* s5 = s4 + (CWW * HH / 4);

        int eslot = 0, ephase = 0;
#pragma unroll 1
        for (int it = 0; it < TOT_STAGES; it++) {
            const int s = it % RING;
            if (it >= RING) {
                mbar_wait_rlx(emptyb(eslot), ephase);
                if (++eslot == RING) { eslot = 0; ephase ^= 1; }
            }
            const int chunk = it >> 5;
            const int c     = it & 31;
            const int off   = c * (POS * 4) + chunk * SLOTS;   // float4 units
            const uint32_t d = smem_b + s * STAGE_BYTES;
            MBAR_EXPECT_TX(fullb(s), (uint32_t)STAGE_BYTES);
            CP_BULK(d + 0 * STREAM_BYTES, s0 + off, STREAM_BYTES, fullb(s));
            CP_BULK(d + 1 * STREAM_BYTES, s1 + off, STREAM_BYTES, fullb(s));
            CP_BULK(d + 2 * STREAM_BYTES, s2 + off, STREAM_BYTES, fullb(s));
            CP_BULK(d + 3 * STREAM_BYTES, s3 + off, STREAM_BYTES, fullb(s));
            CP_BULK(d + 4 * STREAM_BYTES, s4 + off, STREAM_BYTES, fullb(s));
            CP_BULK(d + 5 * STREAM_BYTES, s5 + off, STREAM_BYTES, fullb(s));
        }
        return;
    }
    if (tid >= SLOTS) return;   // dead lanes (196-223, 225-255)

    // ---- consumers ----
    const int v = tid & 3;
    const unsigned shfl_mask = (tid < 192) ? 0xffffffffu : 0x0000000Fu;

    int fslot = 0, fphase = 0;

#pragma unroll 1
    for (int chunk = 0; chunk < NCHUNK; chunk++) {
        float4 acc[G][4];
#pragma unroll
        for (int g = 0; g < G; g++)
#pragma unroll
            for (int u = 0; u < 4; u++)
                acc[g][u] = make_float4(0.f, 0.f, 0.f, 0.f);

#pragma unroll 1
        for (int c = 0; c < C_; c++) {
            mbar_wait_acq(fullb(fslot), fphase);

            const float4* st = reinterpret_cast<const float4*>(
                smem_raw + fslot * STAGE_BYTES);
            float4 mm = st[0 * SLOTS + tid];
            float4 ss = st[1 * SLOTS + tid];
            float4 n0 = st[2 * SLOTS + tid];
            float4 n1 = st[3 * SLOTS + tid];
            float4 n2 = st[4 * SLOTS + tid];
            float4 n3 = st[5 * SLOTS + tid];

            // Reads done -> release the slot for the producer.
            MBAR_ARRIVE(emptyb(fslot));
            if (++fslot == RING) { fslot = 0; fphase ^= 1; }

            float4 vt;
            const float4* wv;

            vt.x = fmaf(ss.x, n0.x, mm.x);
            vt.y = fmaf(ss.y, n0.y, mm.y);
            vt.z = fmaf(ss.z, n0.z, mm.z);
            vt.w = fmaf(ss.w, n0.w, mm.w);
            wv = reinterpret_cast<const float4*>(&sW[((0 * C_ + c) * 4 + v) * 4]);
            fma4(acc[0][0], wv->x, vt);
            fma4(acc[0][1], wv->y, vt);
            fma4(acc[0][2], wv->z, vt);
            fma4(acc[0][3], wv->w, vt);

            vt.x = fmaf(ss.x, n1.x, mm.x);
            vt.y = fmaf(ss.y, n1.y, mm.y);
            vt.z = fmaf(ss.z, n1.z, mm.z);
            vt.w = fmaf(ss.w, n1.w, mm.w);
            wv = reinterpret_cast<const float4*>(&sW[((1 * C_ + c) * 4 + v) * 4]);
            fma4(acc[1][0], wv->x, vt);
            fma4(acc[1][1], wv->y, vt);
            fma4(acc[1][2], wv->z, vt);
            fma4(acc[1][3], wv->w, vt);

            vt.x = fmaf(ss.x, n2.x, mm.x);
            vt.y = fmaf(ss.y, n2.y, mm.y);
            vt.z = fmaf(ss.z, n2.z, mm.z);
            vt.w = fmaf(ss.w, n2.w, mm.w);
            wv = reinterpret_cast<const float4*>(&sW[((2 * C_ + c) * 4 + v) * 4]);
            fma4(acc[2][0], wv->x, vt);
            fma4(acc[2][1], wv->y, vt);
            fma4(acc[2][2], wv->z, vt);
            fma4(acc[2][3], wv->w, vt);

            vt.x = fmaf(ss.x, n3.x, mm.x);
            vt.y = fmaf(ss.y, n3.y, mm.y);
            vt.z = fmaf(ss.z, n3.z, mm.z);
            vt.w = fmaf(ss.w, n3.w, mm.w);
            wv = reinterpret_cast<const float4*>(&sW[((3 * C_ + c) * 4 + v) * 4]);
            fma4(acc[3][0], wv->x, vt);
            fma4(acc[3][1], wv->y, vt);
            fma4(acc[3][2], wv->z, vt);
            fma4(acc[3][3], wv->w, vt);
        }

        // v-contraction across each 4-lane (site) group: 2 butterfly rounds.
#pragma unroll
        for (int g = 0; g < G; g++)
#pragma unroll
            for (int u = 0; u < 4; u++) {
                float4 a = acc[g][u];
                a.x += __shfl_xor_sync(shfl_mask, a.x, 1);
                a.y += __shfl_xor_sync(shfl_mask, a.y, 1);
                a.z += __shfl_xor_sync(shfl_mask, a.z, 1);
                a.w += __shfl_xor_sync(shfl_mask, a.w, 1);
                a.x += __shfl_xor_sync(shfl_mask, a.x, 2);
                a.y += __shfl_xor_sync(shfl_mask, a.y, 2);
                a.z += __shfl_xor_sync(shfl_mask, a.z, 2);
                a.w += __shfl_xor_sync(shfl_mask, a.w, 2);
                acc[g][u] = a;
            }

        const int site = chunk * 49 + (tid >> 2);
        const int j = site / W_;
        const int i = site % W_;
#pragma unroll
        for (int g = 0; g < G; g++) {
            const int nkl = nkl0 + g;
            const int n = nkl / 9;
            const int k = (nkl / 3) % 3;
            const int l = nkl % 3;
            const int r  = 2 * i + k;
            const int cc = 2 * j + l;
            // lane v scatters the u==v float4 as ONE vectorized reduction
            float4 a = (v == 0) ? acc[g][0]
                     : (v == 1) ? acc[g][1]
                     : (v == 2) ? acc[g][2]
                                : acc[g][3];
            float* o = out + ((((size_t)b * BC + n) * OUT_HW + r) * OUT_HW + cc) * HH
                           + v * 4;      // 16B-aligned
            REDV4(o, a);
        }
    }
}

extern "C" void kernel_launch(void* const* d_in, const int* in_sizes, int n_in,
                              void* d_out, int out_size) {
    const float* poses = (const float*)d_in[0];
    const float* var   = (const float*)d_in[1];
    const float* Wt    = (const float*)d_in[2];
    const float* noise = (const float*)d_in[3];
    float* out = (float*)d_out;

    // Allow >48KB dynamic smem (idempotent attribute set; capture-safe).
    cudaFuncSetAttribute(conv_caps_kernel,
                         cudaFuncAttributeMaxDynamicSharedMemorySize, SMEM_BYTES);

    const int out_n4 = out_size / 4;
    const int pt = 256;
    const int pb = (out_n4 + pt - 1) / pt;
    prep_kernel<<<pb, pt>>>(var, out, out_n4);

    dim3 grid(NKLG, BATCH);   // 288 blocks, one resident wave (2 CTAs/SM)
    conv_caps_kernel<<<grid, 256, SMEM_BYTES>>>(poses, Wt, noise, out);
}